// round 11
// baseline (speedup 1.0000x reference)
#include <cuda_runtime.h>
#include <math.h>

#define N_ROWS 65536
#define NB     65536
#define NBLK   64
#define NTHR   256
#define VT     4
#define CAP    1408       // smem slots per block (mean 1024, sd 32 -> 12 sigma)

// ---------------- scratch (device globals; zero-init at load, kernel leaves
// hist/cnt/bar/done zeroed for the next call) --------------------------------
__device__ float    g_e2[N_ROWS], g_e3[N_ROWS];
__device__ unsigned g_hist[NB], g_cnt[NB], g_off[NB];
__device__ unsigned long long g_bsort[N_ROWS];
__device__ float    g_se2[N_ROWS], g_se3[N_ROWS];   // overflow fallback only
__device__ unsigned g_bsum[NBLK];
__device__ double   g_csum2[NBLK], g_csum3[NBLK], g_part[NBLK];
__device__ unsigned g_bar[8];
__device__ unsigned g_done;

__device__ __forceinline__ unsigned bucket_of(float k) {
    k = fminf(fmaxf(k, 0.0f), 0.999999f);
    unsigned b = (unsigned)(k * 65536.0f);
    return b > 65535u ? 65535u : b;
}

// Grid barrier: pure spin (no nanosleep) on an L2-resident counter.
__device__ __forceinline__ void gbar(int i) {
    __syncthreads();
    if (threadIdx.x == 0) {
        __threadfence();
        atomicAdd(&g_bar[i], 1u);
        while (((volatile unsigned*)g_bar)[i] < NBLK) { }
        __threadfence();
    }
    __syncthreads();
}

// ===========================================================================
// K1: per-row cos-sim -> exp, fused ranking histogram, redundant norms.
// 8192 blocks x 256 (1 warp/row). DRAM-bandwidth bound (~75% of peak).
// ===========================================================================
__global__ void __launch_bounds__(256)
k1_main(const float4* __restrict__ x,
        const float4* __restrict__ o2,
        const float4* __restrict__ o3,
        const float*  __restrict__ rank) {
    __shared__ float4 so2[128], so3[128];
    __shared__ float  red[8];
    __shared__ float  s_n2, s_n3;
    int t = threadIdx.x;
    if (t < 128)      so2[t]       = o2[t];
    else              so3[t - 128] = o3[t - 128];
    __syncthreads();

    float a;
    if (t < 128) { float4 v = so2[t];       a = v.x*v.x + v.y*v.y + v.z*v.z + v.w*v.w; }
    else         { float4 v = so3[t - 128]; a = v.x*v.x + v.y*v.y + v.z*v.z + v.w*v.w; }
#pragma unroll
    for (int o = 16; o > 0; o >>= 1) a += __shfl_xor_sync(0xFFFFFFFFu, a, o);
    int warp = t >> 5, lane = t & 31;
    if (lane == 0) red[warp] = a;
    __syncthreads();
    if (t == 0) {
        s_n2 = sqrtf(red[0] + red[1] + red[2] + red[3]);
        s_n3 = sqrtf(red[4] + red[5] + red[6] + red[7]);
    }
    __syncthreads();
    float n2 = s_n2, n3 = s_n3;

    int row = blockIdx.x * 8 + warp;
    const float4* xr = x + (size_t)row * 128;
    float d2 = 0.f, d3 = 0.f, nn = 0.f;
#pragma unroll
    for (int k = 0; k < 4; k++) {
        float4 v = xr[lane + 32 * k];
        float4 p = so2[lane + 32 * k];
        float4 q = so3[lane + 32 * k];
        d2 += v.x * p.x + v.y * p.y + v.z * p.z + v.w * p.w;
        d3 += v.x * q.x + v.y * q.y + v.z * q.z + v.w * q.w;
        nn += v.x * v.x + v.y * v.y + v.z * v.z + v.w * v.w;
    }
#pragma unroll
    for (int o = 16; o > 0; o >>= 1) {
        d2 += __shfl_xor_sync(0xFFFFFFFFu, d2, o);
        d3 += __shfl_xor_sync(0xFFFFFFFFu, d3, o);
        nn += __shfl_xor_sync(0xFFFFFFFFu, nn, o);
    }
    if (lane == 0) {
        float nx = sqrtf(nn);
        g_e2[row] = expf(d2 / fmaxf(nx * n2, 1e-8f));
        g_e3[row] = expf(d3 / fmaxf(nx * n3, 1e-8f));
        atomicAdd(&g_hist[bucket_of(rank[row])], 1u);
    }
}

// ===========================================================================
// K2 (fused, 64 x 256, VT=4): hist scan -> scatter -> place(smem) ->
// chunk-offset scan -> prefix+logs -> final. 4 grid barriers.
// ===========================================================================
__global__ void __launch_bounds__(256)
k2_fused(const float* __restrict__ rank, float* __restrict__ out) {
    __shared__ float    s_e2[CAP], s_e3[CAP];
    __shared__ unsigned s_scan[NBLK];
    __shared__ unsigned s_wtu[8];
    __shared__ double   s_wt2[8], s_wt3[8];
    __shared__ double   s_c2[NBLK], s_c3[NBLK];
    __shared__ bool     amLast;

    int t = threadIdx.x, blk = blockIdx.x;
    int warp = t >> 5, lane = t & 31;
    int b0 = (blk * NTHR + t) * VT;

    // ---- Phase A: exclusive scan of g_hist ---------------------------------
    uint4 hv = __ldcg((const uint4*)&g_hist[b0]);
    unsigned hsum = hv.x + hv.y + hv.z + hv.w;
    {
        uint4 z = {0u,0u,0u,0u};
        *(uint4*)&g_hist[b0] = z;                 // cleanup for next call
    }
    unsigned v = hsum;
#pragma unroll
    for (int o = 1; o < 32; o <<= 1) {
        unsigned u = __shfl_up_sync(0xFFFFFFFFu, v, o);
        if (lane >= o) v += u;
    }
    if (lane == 31) s_wtu[warp] = v;
    __syncthreads();
    if (t < 8) {
        unsigned x = s_wtu[t];
#pragma unroll
        for (int o = 1; o < 8; o <<= 1) {
            unsigned u = __shfl_up_sync(0xFFu, x, o);
            if (t >= o) x += u;
        }
        s_wtu[t] = x;
    }
    __syncthreads();
    unsigned incl = v + (warp ? s_wtu[warp - 1] : 0u);
    unsigned exth = incl - hsum;
    if (t == NTHR - 1) g_bsum[blk] = incl;
    gbar(0);
    // redundant scan of 64 block sums
    if (t < NBLK) s_scan[t] = __ldcg(&g_bsum[t]);
    __syncthreads();
#pragma unroll
    for (int o = 1; o < NBLK; o <<= 1) {
        unsigned u = (t >= o && t < NBLK) ? s_scan[t - o] : 0u;
        __syncthreads();
        if (t < NBLK) s_scan[t] += u;
        __syncthreads();
    }
    unsigned blockBase = (blk > 0) ? s_scan[blk - 1] : 0u;
    unsigned n_blk     = s_scan[blk] - blockBase;
    unsigned off0 = blockBase + exth;
    uint4 ov;
    ov.x = off0;
    ov.y = ov.x + hv.x;
    ov.z = ov.y + hv.y;
    ov.w = ov.z + hv.z;
    *(uint4*)&g_off[b0] = ov;
    gbar(1);

    // ---- Phase B: scatter packed (key,idx); 4 independent chains -----------
    {
        float4 kv = *(const float4*)&rank[b0];
        float kk[VT] = {kv.x, kv.y, kv.z, kv.w};
#pragma unroll
        for (int j = 0; j < VT; j++) {
            unsigned b = bucket_of(kk[j]);
            unsigned slot = __ldcg(&g_off[b]) + atomicAdd(&g_cnt[b], 1u);
            g_bsort[slot] = ((unsigned long long)__float_as_uint(kk[j]) << 32)
                            | (unsigned)(b0 + j);
        }
    }
    gbar(2);

    // ---- Phase C: within-bucket rank; place into SMEM; fused block sums ----
    bool fits = (n_blk <= CAP);
    double sum2 = 0.0, sum3 = 0.0;
    {
        unsigned hj[VT]   = {hv.x, hv.y, hv.z, hv.w};
        unsigned offj[VT] = {ov.x, ov.y, ov.z, ov.w};
#pragma unroll
        for (int j = 0; j < VT; j++) {
            unsigned h = hj[j];
            if (h == 0u) continue;
            unsigned base = offj[j];
            unsigned lb   = base - blockBase;
            if (h == 1u) {
                unsigned idx = (unsigned)(__ldcg(&g_bsort[base]) & 0xFFFFFFFFu);
                float e2v = g_e2[idx], e3v = g_e3[idx];
                sum2 += e2v; sum3 += e3v;
                if (fits) { s_e2[lb] = e2v; s_e3[lb] = e3v; }
                else      { g_se2[base] = e2v; g_se3[base] = e3v; }
            } else if (h <= 8u) {
                unsigned long long loc[8];
#pragma unroll
                for (int l = 0; l < 8; l++)
                    loc[l] = (l < (int)h) ? __ldcg(&g_bsort[base + l])
                                          : 0xFFFFFFFFFFFFFFFFull;
#pragma unroll
                for (int a2 = 0; a2 < 8; a2++) {
                    if (a2 < (int)h) {
                        unsigned long long kj = loc[a2];
                        unsigned r = 0;
#pragma unroll
                        for (int l = 0; l < 8; l++) r += (loc[l] < kj);
                        unsigned idx = (unsigned)(kj & 0xFFFFFFFFu);
                        float e2v = g_e2[idx], e3v = g_e3[idx];
                        sum2 += e2v; sum3 += e3v;
                        if (fits) { s_e2[lb + r] = e2v; s_e3[lb + r] = e3v; }
                        else      { g_se2[base + r] = e2v; g_se3[base + r] = e3v; }
                    }
                }
            } else {                              // Poisson tail, essentially never
                for (unsigned a2 = 0; a2 < h; a2++) {
                    unsigned long long kj = __ldcg(&g_bsort[base + a2]);
                    unsigned r = 0;
                    for (unsigned l = 0; l < h; l++)
                        r += (__ldcg(&g_bsort[base + l]) < kj);
                    unsigned idx = (unsigned)(kj & 0xFFFFFFFFu);
                    float e2v = g_e2[idx], e3v = g_e3[idx];
                    sum2 += e2v; sum3 += e3v;
                    if (fits) { s_e2[lb + r] = e2v; s_e3[lb + r] = e3v; }
                    else      { g_se2[base + r] = e2v; g_se3[base + r] = e3v; }
                }
            }
        }
        uint4 z = {0u,0u,0u,0u};
        *(uint4*)&g_cnt[b0] = z;                  // cleanup for next call
    }
    // block reduce of (sum2,sum3) -> g_csum
    {
        double a2 = sum2, a3 = sum3;
#pragma unroll
        for (int o = 16; o > 0; o >>= 1) {
            a2 += __shfl_xor_sync(0xFFFFFFFFu, a2, o);
            a3 += __shfl_xor_sync(0xFFFFFFFFu, a3, o);
        }
        if (lane == 0) { s_wt2[warp] = a2; s_wt3[warp] = a3; }
        __syncthreads();
        if (t == 0) {
            double c2 = 0.0, c3 = 0.0;
            for (int j = 0; j < 8; j++) { c2 += s_wt2[j]; c3 += s_wt3[j]; }
            g_csum2[blk] = c2; g_csum3[blk] = c3;
        }
    }
    gbar(3);

    // ---- Phase E: chunk-offset scan (redundant 64) + rounds of prefix+log --
    if (t < NBLK) { s_c2[t] = __ldcg(&g_csum2[t]); s_c3[t] = __ldcg(&g_csum3[t]); }
    __syncthreads();
#pragma unroll
    for (int o = 1; o < NBLK; o <<= 1) {
        double u2 = (t >= o && t < NBLK) ? s_c2[t - o] : 0.0;
        double u3 = (t >= o && t < NBLK) ? s_c3[t - o] : 0.0;
        __syncthreads();
        if (t < NBLK) { s_c2[t] += u2; s_c3[t] += u3; }
        __syncthreads();
    }
    double tot2 = s_c2[NBLK - 1], tot3 = s_c3[NBLK - 1];
    double carry2 = (blk > 0) ? s_c2[blk - 1] : 0.0;
    double carry3 = (blk > 0) ? s_c3[blk - 1] : 0.0;

    double ls = 0.0;
    int R = (int)((n_blk + NTHR - 1) / NTHR);
    for (int r = 0; r < R; r++) {
        int i = r * NTHR + t;
        bool valid = i < (int)n_blk;
        double e2 = 0.0, e3 = 0.0;
        if (valid) {
            if (fits) { e2 = (double)s_e2[i];             e3 = (double)s_e3[i]; }
            else      { e2 = (double)g_se2[blockBase + i]; e3 = (double)g_se3[blockBase + i]; }
        }
        double v2 = e2, v3 = e3;
#pragma unroll
        for (int o = 1; o < 32; o <<= 1) {
            double u2 = __shfl_up_sync(0xFFFFFFFFu, v2, o);
            double u3 = __shfl_up_sync(0xFFFFFFFFu, v3, o);
            if (lane >= o) { v2 += u2; v3 += u3; }
        }
        if (lane == 31) { s_wt2[warp] = v2; s_wt3[warp] = v3; }
        __syncthreads();
        if (t < 8) {
            double x2 = s_wt2[t], x3 = s_wt3[t];
#pragma unroll
            for (int o = 1; o < 8; o <<= 1) {
                double u2 = __shfl_up_sync(0xFFu, x2, o);
                double u3 = __shfl_up_sync(0xFFu, x3, o);
                if (t >= o) { x2 += u2; x3 += u3; }
            }
            s_wt2[t] = x2; s_wt3[t] = x3;
        }
        __syncthreads();
        double incl2 = v2 + (warp ? s_wt2[warp - 1] : 0.0);
        double incl3 = v3 + (warp ? s_wt3[warp - 1] : 0.0);
        if (valid)
            ls += (double)logf((float)(carry2 + incl2)) +
                  (double)logf((float)(carry3 + incl3));
        carry2 += s_wt2[7];
        carry3 += s_wt3[7];
        __syncthreads();                          // s_wt reuse next round
    }

    // block reduce of ls -> g_part
#pragma unroll
    for (int o = 16; o > 0; o >>= 1) ls += __shfl_xor_sync(0xFFFFFFFFu, ls, o);
    if (lane == 0) s_wt2[warp] = ls;
    __syncthreads();
    if (t == 0) {
        double s = 0.0;
        for (int j = 0; j < 8; j++) s += s_wt2[j];
        g_part[blk] = s;
    }

    // ---- Final: last block reduces partials, writes out, resets state ------
    if (t == 0) {
        __threadfence();
        amLast = (atomicAdd(&g_done, 1u) == NBLK - 1);
    }
    __syncthreads();
    if (amLast) {
        double p = (t < NBLK) ? __ldcg(&g_part[t]) : 0.0;
#pragma unroll
        for (int o = 16; o > 0; o >>= 1) p += __shfl_xor_sync(0xFFFFFFFFu, p, o);
        __syncthreads();
        if (lane == 0) s_wt2[warp] = p;
        __syncthreads();
        if (t == 0) {
            double s = 0.0;
            for (int j = 0; j < 8; j++) s += s_wt2[j];
            out[0] = (float)((double)N_ROWS * (log(tot2) + log(tot3)) - s);
            g_done = 0u;
        }
        if (t < 8) g_bar[t] = 0u;
    }
}

extern "C" void kernel_launch(void* const* d_in, const int* in_sizes, int n_in,
                              void* d_out, int out_size) {
    const float* o1   = (const float*)d_in[0];  // [65536, 512]
    const float* o2   = (const float*)d_in[1];  // [1, 512]
    const float* o3   = (const float*)d_in[2];  // [1, 512]
    const float* rank = (const float*)d_in[3];  // [65536]
    float* out = (float*)d_out;

    k1_main<<<N_ROWS / 8, 256>>>((const float4*)o1, (const float4*)o2,
                                 (const float4*)o3, rank);
    k2_fused<<<NBLK, NTHR>>>(rank, out);
}